// round 13
// baseline (speedup 1.0000x reference)
#include <cuda_runtime.h>
#include <cstdint>

#define BATCH  64
#define MROWS  2048
#define DIM    512
#define NCHUNK 64            // MROWS / 32 rows-per-chunk
#define NSEG   8             // blocks per batch: 64 % 8 == 0 -> perfect balance

// Per-(batch,seg) packed partial: (dist2_bits << 32) | (0xFFFFFFFF - m).
// Every slot is written every launch -> no init kernel needed.
__device__ unsigned long long g_part[BATCH * NSEG];
// Per-batch completion counter; last block resets it to 0 (graph-replay safe).
__device__ unsigned int g_count[BATCH];

static __device__ __forceinline__ unsigned long long umax64(
    unsigned long long a, unsigned long long b) { return a > b ? a : b; }

// Grid: BATCH*NSEG = 512 blocks, single wave at occ 4 (592 slots).
// Each block serves one batch, exactly 8 chunks (512 KB stream), with a
// row-prefetch pipeline that crosses chunk boundaries (no drain until end).
__global__ __launch_bounds__(256, 4) void knn_fused_kernel(
    const float* __restrict__ inputs,
    const float* __restrict__ buffer,
    float* __restrict__ out)
{
    __shared__ float4 q4s[DIM / 4];              // 2 KB query
    __shared__ unsigned long long wbest[8];
    __shared__ unsigned int s_is_last;
    __shared__ unsigned int s_m;

    const int bx   = blockIdx.x;
    const int b    = bx >> 3;                    // bx / NSEG
    const int seg  = bx & 7;                     // bx % NSEG
    const int tid  = threadIdx.x;
    const int warp = tid >> 5;
    const int lane = tid & 31;

    // Stage query into smem once per block (coalesced float4).
    const float4* qin = reinterpret_cast<const float4*>(inputs + (size_t)b * DIM);
    for (int i = tid; i < DIM / 4; i += blockDim.x) q4s[i] = qin[i];
    __syncthreads();

    const float* buf_b = buffer + (size_t)b * MROWS * DIM;

    // Prefetch first row of first chunk (m = seg*32 + warp*4).
    float4 va[4], vb[4];
    {
        const float4* r0 = reinterpret_cast<const float4*>(
            buf_b + (size_t)(seg * 32 + warp * 4) * DIM);
        #pragma unroll
        for (int j = 0; j < 4; j++) va[j] = __ldcs(&r0[lane + 32 * j]);
    }

    unsigned long long local = 0ULL;

    for (int cc = 0; cc < NCHUNK / NSEG; cc++) {
        const int m0 = (seg + cc * NSEG) * 32 + warp * 4;

        #pragma unroll
        for (int k = 0; k < 4; k++) {
            // Prefetch the next pipeline row. INVARIANT: the prefetched row
            // index must equal the row consumed at the next iteration:
            //   within chunk (k<3):       next row = m0 + k + 1
            //   chunk boundary (k==3):    next row = next chunk's row 0 for
            //                             this warp = m0 + NSEG*32
            if (k < 3) {
                const float4* rn = reinterpret_cast<const float4*>(
                    buf_b + (size_t)(m0 + k + 1) * DIM);
                #pragma unroll
                for (int j = 0; j < 4; j++) vb[j] = __ldcs(&rn[lane + 32 * j]);
            } else if (cc < NCHUNK / NSEG - 1) {
                const float4* rn = reinterpret_cast<const float4*>(
                    buf_b + (size_t)(m0 + NSEG * 32) * DIM);
                #pragma unroll
                for (int j = 0; j < 4; j++) vb[j] = __ldcs(&rn[lane + 32 * j]);
            }

            float acc0 = 0.0f, acc1 = 0.0f, acc2 = 0.0f, acc3 = 0.0f;
            #pragma unroll
            for (int j = 0; j < 4; j++) {
                float4 q = q4s[lane + 32 * j];   // LDS.128, conflict-free
                float4 v = va[j];
                float d0 = v.x - q.x;
                float d1 = v.y - q.y;
                float d2 = v.z - q.z;
                float d3 = v.w - q.w;
                acc0 = fmaf(d0, d0, acc0);
                acc1 = fmaf(d1, d1, acc1);
                acc2 = fmaf(d2, d2, acc2);
                acc3 = fmaf(d3, d3, acc3);
            }
            float acc = (acc0 + acc1) + (acc2 + acc3);

            #pragma unroll
            for (int off = 16; off > 0; off >>= 1)
                acc += __shfl_xor_sync(0xFFFFFFFFu, acc, off);

            // dist2 >= 0 -> float bits order-preserving; ~m tie-breaks to
            // the smallest m (argmax first-index semantics).
            unsigned long long pack =
                ((unsigned long long)__float_as_uint(acc) << 32) |
                (unsigned long long)(0xFFFFFFFFu - (unsigned)(m0 + k));
            local = umax64(local, pack);

            #pragma unroll
            for (int j = 0; j < 4; j++) va[j] = vb[j];
        }
    }

    if (lane == 0) wbest[warp] = local;
    __syncthreads();

    // ---- Block reduce + completion protocol ----
    if (tid == 0) {
        unsigned long long blk = wbest[0];
        #pragma unroll
        for (int w = 1; w < 8; w++) blk = umax64(blk, wbest[w]);
        g_part[b * NSEG + seg] = blk;
        __threadfence();                          // publish partial before count
        unsigned int old = atomicAdd(&g_count[b], 1u);
        s_is_last = (old == NSEG - 1) ? 1u : 0u;
    }
    __syncthreads();

    // ---- Last block for this batch: reduce 8 partials + gather winning row ----
    if (s_is_last) {
        if (warp == 0) {
            __threadfence();                      // acquire partials
            unsigned long long mx =
                (lane < NSEG) ? g_part[b * NSEG + lane] : 0ULL;
            #pragma unroll
            for (int off = 16; off > 0; off >>= 1) {
                unsigned long long o = __shfl_xor_sync(0xFFFFFFFFu, mx, off);
                mx = umax64(mx, o);
            }
            if (lane == 0) {
                s_m = 0xFFFFFFFFu - (unsigned)(mx & 0xFFFFFFFFu);
                g_count[b] = 0;                   // restore invariant for next replay
            }
        }
        __syncthreads();
        const unsigned m = s_m;
        const float4* src = reinterpret_cast<const float4*>(
            buffer + ((size_t)b * MROWS + m) * DIM);
        float4* dst = reinterpret_cast<float4*>(out + (size_t)b * DIM);
        if (tid < DIM / 4) dst[tid] = src[tid];
    }
}

extern "C" void kernel_launch(void* const* d_in, const int* in_sizes, int n_in,
                              void* d_out, int out_size)
{
    const float* inputs = (const float*)d_in[0];   // [B, D]
    const float* buffer = (const float*)d_in[1];   // [B, M, D]
    float* out = (float*)d_out;                    // [B, D]

    knn_fused_kernel<<<BATCH * NSEG, 256>>>(inputs, buffer, out);
}

// round 14
// speedup vs baseline: 1.0049x; 1.0049x over previous
#include <cuda_runtime.h>
#include <cstdint>

#define BATCH  64
#define MROWS  2048
#define DIM    512
#define ROWB   (DIM * 4)                 // 2048 B per row
#define NSEG   8                         // blocks per batch (64 % 8 == 0)
#define NCHUNK 64                        // chunks of 32 rows
#define CPB    (NCHUNK / NSEG)           // 8 chunks per block
#define STAGE_ROWS  8
#define STAGE_BYTES (STAGE_ROWS * ROWB)  // 16 KB
#define NSTAGE 2
#define NSTAGES_TOTAL (CPB * 4)          // 32 stages of 8 rows per block

// Per-(batch,seg) packed partial: (dist2_bits << 32) | (0xFFFFFFFF - m).
__device__ unsigned long long g_part[BATCH * NSEG];
// Per-batch completion counter; last block resets it (graph-replay safe).
__device__ unsigned int g_count[BATCH];

static __device__ __forceinline__ unsigned long long umax64(
    unsigned long long a, unsigned long long b) { return a > b ? a : b; }

static __device__ __forceinline__ uint32_t s2u(const void* p) {
    return (uint32_t)__cvta_generic_to_shared(p);
}
static __device__ __forceinline__ void mbar_init(uint32_t a, uint32_t cnt) {
    asm volatile("mbarrier.init.shared.b64 [%0], %1;" :: "r"(a), "r"(cnt) : "memory");
}
static __device__ __forceinline__ void mbar_expect_tx(uint32_t a, uint32_t bytes) {
    asm volatile("mbarrier.arrive.expect_tx.shared.b64 _, [%0], %1;"
                 :: "r"(a), "r"(bytes) : "memory");
}
static __device__ __forceinline__ void mbar_arrive(uint32_t a) {
    asm volatile("mbarrier.arrive.shared.b64 _, [%0];" :: "r"(a) : "memory");
}
static __device__ __forceinline__ void mbar_wait(uint32_t a, uint32_t ph) {
    asm volatile(
        "{\n\t.reg .pred P;\n\t"
        "WL_%=:\n\t"
        "mbarrier.try_wait.parity.acquire.cta.shared::cta.b64 P, [%0], %1, 0x989680;\n\t"
        "@P bra.uni WD_%=;\n\t"
        "bra.uni WL_%=;\n\t"
        "WD_%=:\n\t}"
        :: "r"(a), "r"(ph) : "memory");
}
static __device__ __forceinline__ void bulk_g2s(uint32_t dst, const void* src,
                                                uint32_t bytes, uint32_t mbar) {
    asm volatile(
        "cp.async.bulk.shared::cta.global.mbarrier::complete_tx::bytes [%0], [%1], %2, [%3];"
        :: "r"(dst), "l"(src), "r"(bytes), "r"(mbar) : "memory");
}

// Grid: BATCH*NSEG = 512 blocks; block = 288 threads = 8 consumer warps + 1
// producer warp. Producer streams 16KB stages via cp.async.bulk into a
// 2-stage smem ring; consumer warp w reduces row w of each stage.
__global__ __launch_bounds__(288, 5) void knn_tma_kernel(
    const float* __restrict__ inputs,
    const float* __restrict__ buffer,
    float* __restrict__ out)
{
    __shared__ __align__(128) char stage_mem[NSTAGE * STAGE_BYTES];   // 32 KB
    __shared__ float4 q4s[DIM / 4];                                   // 2 KB
    __shared__ unsigned long long mbar_full[NSTAGE];
    __shared__ unsigned long long mbar_empty[NSTAGE];
    __shared__ unsigned long long wbest[8];
    __shared__ unsigned int s_is_last;
    __shared__ unsigned int s_m;

    const int bx   = blockIdx.x;
    const int b    = bx >> 3;                    // bx / NSEG
    const int seg  = bx & 7;                     // bx % NSEG
    const int tid  = threadIdx.x;
    const int warp = tid >> 5;
    const int lane = tid & 31;

    const float* buf_b = buffer + (size_t)b * MROWS * DIM;

    // Stage query into smem once (coalesced float4, all 288 threads help).
    const float4* qin = reinterpret_cast<const float4*>(inputs + (size_t)b * DIM);
    for (int i = tid; i < DIM / 4; i += 288) q4s[i] = qin[i];

    if (tid == 0) {
        #pragma unroll
        for (int s = 0; s < NSTAGE; s++) {
            mbar_init(s2u(&mbar_full[s]), 1);     // producer's expect-arrive
            mbar_init(s2u(&mbar_empty[s]), 256);  // 8 consumer warps
        }
    }
    __syncthreads();                              // barriers + q visible

    if (warp == 8) {
        // ---------------- producer (lane 0 only issues) ----------------
        if (lane == 0) {
            for (int it = 0; it < NSTAGES_TOTAL; it++) {
                const int s = it & 1;
                if (it >= NSTAGE) {
                    // buffer s free once consumers finish stage it-2
                    mbar_wait(s2u(&mbar_empty[s]), ((it - NSTAGE) >> 1) & 1);
                }
                const int t = it >> 2, sub = it & 3;
                const int row0 = (seg + t * NSEG) * 32 + sub * STAGE_ROWS;
                mbar_expect_tx(s2u(&mbar_full[s]), STAGE_BYTES);
                bulk_g2s(s2u(stage_mem) + s * STAGE_BYTES,
                         (const char*)buf_b + (size_t)row0 * ROWB,
                         STAGE_BYTES, s2u(&mbar_full[s]));
            }
        }
    } else {
        // ---------------- consumers: 8 warps, one row per warp/stage ----
        unsigned long long local = 0ULL;
        for (int it = 0; it < NSTAGES_TOTAL; it++) {
            const int s = it & 1;
            mbar_wait(s2u(&mbar_full[s]), (it >> 1) & 1);

            const float4* row = reinterpret_cast<const float4*>(
                stage_mem + s * STAGE_BYTES + warp * ROWB);

            float acc0 = 0.0f, acc1 = 0.0f, acc2 = 0.0f, acc3 = 0.0f;
            #pragma unroll
            for (int j = 0; j < 4; j++) {
                float4 v = row[lane + 32 * j];    // LDS.128, conflict-free
                float4 q = q4s[lane + 32 * j];
                float d0 = v.x - q.x;
                float d1 = v.y - q.y;
                float d2 = v.z - q.z;
                float d3 = v.w - q.w;
                acc0 = fmaf(d0, d0, acc0);
                acc1 = fmaf(d1, d1, acc1);
                acc2 = fmaf(d2, d2, acc2);
                acc3 = fmaf(d3, d3, acc3);
            }
            float acc = (acc0 + acc1) + (acc2 + acc3);
            #pragma unroll
            for (int off = 16; off > 0; off >>= 1)
                acc += __shfl_xor_sync(0xFFFFFFFFu, acc, off);

            mbar_arrive(s2u(&mbar_empty[s]));     // reads done; buffer reusable

            const int t = it >> 2, sub = it & 3;
            const int m = (seg + t * NSEG) * 32 + sub * STAGE_ROWS + warp;
            // dist2 >= 0 -> float bits order-preserving; ~m tie-breaks to
            // the smallest m (argmax first-index semantics).
            unsigned long long pack =
                ((unsigned long long)__float_as_uint(acc) << 32) |
                (unsigned long long)(0xFFFFFFFFu - (unsigned)m);
            local = umax64(local, pack);
        }
        if (lane == 0) wbest[warp] = local;
    }
    __syncthreads();

    // ---- Block reduce + completion protocol ----
    if (tid == 0) {
        unsigned long long blk = wbest[0];
        #pragma unroll
        for (int w = 1; w < 8; w++) blk = umax64(blk, wbest[w]);
        g_part[b * NSEG + seg] = blk;
        __threadfence();                          // publish partial before count
        unsigned int old = atomicAdd(&g_count[b], 1u);
        s_is_last = (old == NSEG - 1) ? 1u : 0u;
    }
    __syncthreads();

    // ---- Last block for this batch: reduce 8 partials + gather winner ----
    if (s_is_last) {
        if (warp == 0) {
            __threadfence();                      // acquire partials
            unsigned long long mx =
                (lane < NSEG) ? g_part[b * NSEG + lane] : 0ULL;
            #pragma unroll
            for (int off = 16; off > 0; off >>= 1) {
                unsigned long long o = __shfl_xor_sync(0xFFFFFFFFu, mx, off);
                mx = umax64(mx, o);
            }
            if (lane == 0) {
                s_m = 0xFFFFFFFFu - (unsigned)(mx & 0xFFFFFFFFu);
                g_count[b] = 0;                   // restore invariant for replay
            }
        }
        __syncthreads();
        const unsigned m = s_m;
        const float4* src = reinterpret_cast<const float4*>(
            buffer + ((size_t)b * MROWS + m) * DIM);
        float4* dst = reinterpret_cast<float4*>(out + (size_t)b * DIM);
        if (tid < DIM / 4) dst[tid] = src[tid];
    }
}

extern "C" void kernel_launch(void* const* d_in, const int* in_sizes, int n_in,
                              void* d_out, int out_size)
{
    const float* inputs = (const float*)d_in[0];   // [B, D]
    const float* buffer = (const float*)d_in[1];   // [B, M, D]
    float* out = (float*)d_out;                    // [B, D]

    knn_tma_kernel<<<BATCH * NSEG, 288>>>(inputs, buffer, out);
}